// round 14
// baseline (speedup 1.0000x reference)
#include <cuda_runtime.h>
#include <math.h>

#define W 512
#define F 257
#define HOP 128
#define MAXT 1300

typedef unsigned long long ull;
#define SGNM 0x8000000080000000ULL

__device__ __forceinline__ float ex2(float x) {
    float r; asm("ex2.approx.ftz.f32 %0, %1;" : "=f"(r) : "f"(x)); return r;
}
__device__ __forceinline__ float lg2(float x) {
    float r; asm("lg2.approx.ftz.f32 %0, %1;" : "=f"(r) : "f"(x)); return r;
}
__device__ __forceinline__ ull pack2(float lo, float hi) {
    ull r; asm("mov.b64 %0, {%1, %2};" : "=l"(r) : "f"(lo), "f"(hi)); return r;
}
__device__ __forceinline__ void unpack2(ull v, float &lo, float &hi) {
    asm("mov.b64 {%0, %1}, %2;" : "=f"(lo), "=f"(hi) : "l"(v));
}
__device__ __forceinline__ void ffma2(ull &acc, ull a, ull b) {
    asm("fma.rn.f32x2 %0, %1, %2, %0;" : "+l"(acc) : "l"(a), "l"(b));
}

// ---- static device scratch (zero-init; self-resetting each run) ----
struct Ctl { unsigned int pmax; unsigned int done; unsigned int done2; };
__device__ Ctl   g_ctl;
__device__ float g_lpart[MAXT];
__device__ float g_bark[F], g_dshift[F], g_athpow[F];

// ---------------------------------------------------------------------------
// Fully fused: per-CTA frame DFT (smem-resident) -> grid spin barrier (one
// wave guaranteed by launch_bounds+smem) -> threshold+loss -> last-CTA final.
// ---------------------------------------------------------------------------
__global__ void __launch_bounds__(128, 9) fused_kernel(
    float* __restrict__ out,
    const float* __restrict__ xadv, const float* __restrict__ xref,
    int T, int N)
{
    __shared__ __align__(16) char smbuf[18976];
    // phase-1 views
    ulonglong2* tw  = (ulonglong2*)(smbuf);             // [544] twiddles
    float* xr = (float*)(smbuf + 8704);                 // [512]
    float* xd = (float*)(smbuf + 10752);                // [512]
    ulonglong2* eoE = (ulonglong2*)(smbuf + 12800);     // [128]
    ulonglong2* eoO = (ulonglong2*)(smbuf + 14848);     // [128]
    float* pw  = (float*)(smbuf + 16896);               // [257] Pr -> scaled
    float* pdl = (float*)(smbuf + 17936);               // [257] delta power
    // phase-2 overlay (inside tw region; written only after the barrier)
    float4* msk = (float4*)(smbuf);                     // [128]
    float2* um  = (float2*)(smbuf + 2048);              // [129]
    float*  mcv = (float*)(smbuf + 3088);               // [128]
    short*  order = (short*)(smbuf + 3600);             // [128]
    short*  slim  = (short*)(smbuf + 3856);             // [128]
    short*  sbs   = (short*)(smbuf + 4376);             // [257]
    short*  cum   = (short*)(smbuf + 4896);             // [257]
    unsigned char* mark  = (unsigned char*)(smbuf + 5416);  // [258]
    unsigned char* keepf = (unsigned char*)(smbuf + 5680);  // [128]
    float* sb  = (float*)(smbuf + 5808);                // [257]
    float* ath = (float*)(smbuf + 6840);                // [257]

    __shared__ float  edge[6];
    __shared__ float  r1[4], r2[4], r3[4];
    __shared__ double dred[4];
    __shared__ int    cnt[8], cbase[8];
    __shared__ int    nsh, Ksh, slast;
    __shared__ float  sSC;

    const float LG  = 0.33219280948873623f;   // 0.1*log2(10)
    const float SLP = 27.f * LG;
    const float DB2 = 3.0102999566398120f;    // 10/log2(10)
    const float gw2 = 1.0172526041666667e-5f; // (8/3)/512^2

    int tid = threadIdx.x;
    int w = tid >> 5, l = tid & 31;
    int t = blockIdx.x;
    int base = t * HOP;

    // ---- phase 1: load frame, twiddles, scattered constant tables ----
    for (int i = tid; i < 512; i += 128) {
        float r = xref[base + i], a = xadv[base + i];
        xr[i] = r; xd[i] = a - r;
    }
    for (int k = tid; k < 512; k += 128) {
        float s, c;
        sincospif((float)k * (1.f / 256.f), &s, &c);
        int pk = k + (k >> 4);
        ulonglong2 u; u.x = pack2(c, c); u.y = pack2(s, s);
        tw[pk] = u;
    }
    if (t < F && tid == 0) {
        double freq = (double)t * (8000.0 / 256.0);
        double bark = 13.0 * atan(0.00076 * freq)
                    + 3.5  * atan((freq / 7500.0) * (freq / 7500.0));
        float bf = (float)bark;
        g_bark[t]   = bf;
        g_dshift[t] = -6.025f - 0.275f * bf;
        float ap = 0.f;
        if (freq >= 20.0 && freq <= 20000.0) {
            double fk = freq * 0.001;
            double a = 3.64 * pow(fk, -0.8)
                     - 6.5  * exp(-0.6 * (fk - 3.3) * (fk - 3.3))
                     + 0.001 * fk * fk * fk * fk - 12.0;
            ap = exp10f((float)a * 0.1f);
        }
        g_athpow[t] = ap;
    }
    __syncthreads();

    // eo build (n = tid)
    {
        int n = tid;
        if (n == 0) {
            edge[0] = xr[256];
            edge[1] = (xr[128] + xr[384]) * 0.5f;
            edge[2] = (xr[128] - xr[384]) * 0.5f;
            edge[3] = xd[256];
            edge[4] = (xd[128] + xd[384]) * 0.5f;
            edge[5] = (xd[128] - xd[384]) * 0.5f;
        } else {
            float h1 = 0.5f - 0.5f * cospif((float)n * (1.f / 256.f));
            float h2 = 0.5f - 0.5f * cospif((float)(256 - n) * (1.f / 256.f));
            float a1 = xr[n], a2 = xr[512 - n], a3 = xr[256 - n], a4 = xr[256 + n];
            float b1 = xd[n], b2 = xd[512 - n], b3 = xd[256 - n], b4 = xd[256 + n];
            float p1r = (a1 + a2) * h1, p2r = (a3 + a4) * h2;
            float q1r = (a1 - a2) * h1, q2r = (a3 - a4) * h2;
            float p1d = (b1 + b2) * h1, p2d = (b3 + b4) * h2;
            float q1d = (b1 - b2) * h1, q2d = (b3 - b4) * h2;
            ulonglong2 ue, uo;
            ue.x = pack2(p1r + p2r, p1d + p2d);
            ue.y = pack2(q1r - q2r, q1d - q2d);
            uo.x = pack2(p1r - p2r, p1d - p2d);
            uo.y = pack2(q1r + q2r, q1d + q2d);
            eoE[n] = ue; eoO[n] = uo;
        }
    }
    __syncthreads();

    // DFT: thread handles bins f = 2m+par and f+128 (rotation trick)
    int m = tid & 63, par = tid >> 6;
    int f = 2 * m + par;
    float sgn = (m & 1) ? -1.f : 1.f;
    const ulonglong2* eo = par ? eoO : eoE;

    ull aR, aI, bR, bI;
    if (par == 0) {
        aR = pack2(fmaf(sgn, edge[1], edge[0]), fmaf(sgn, edge[4], edge[3]));
        aI = 0; bR = aR; bI = 0;
    } else {
        aR = pack2(-edge[0], -edge[3]);
        aI = pack2(sgn * edge[2], sgn * edge[5]);
        bR = aR; bI = aI;
    }
    int k = f;
#define DFT_STEP(NN, RMODE) {                                          \
        ulonglong2 cs = tw[k + (k >> 4)];                              \
        ull cc = cs.x, ss = cs.y;                                      \
        ulonglong2 v = eo[NN];                                         \
        ffma2(aR, v.x, cc); ffma2(aI, v.y, ss);                        \
        if (RMODE == 0) { ffma2(bR, v.x, cc);        ffma2(bI, v.y, ss); }        \
        if (RMODE == 1) { ffma2(bR, v.x, ss ^ SGNM); ffma2(bI, v.y, cc); }        \
        if (RMODE == 2) { ffma2(bR, v.x, cc ^ SGNM); ffma2(bI, v.y, ss ^ SGNM); } \
        if (RMODE == 3) { ffma2(bR, v.x, ss);        ffma2(bI, v.y, cc ^ SGNM); } \
        k = (k + f) & 511; }
    for (int n = 1; n + 3 < 128; n += 4) {
        DFT_STEP(n, 1) DFT_STEP(n + 1, 2) DFT_STEP(n + 2, 3) DFT_STEP(n + 3, 0)
    }
    DFT_STEP(125, 1) DFT_STEP(126, 2) DFT_STEP(127, 3)
#undef DFT_STEP

    float lmax;
    {
        float rr, rd, ii, id_;
        unpack2(aR, rr, rd); unpack2(aI, ii, id_);
        float Pa = gw2 * (rr * rr + ii * ii);
        pw[f] = Pa;
        pdl[f] = gw2 * (rd * rd + id_ * id_);
        unpack2(bR, rr, rd); unpack2(bI, ii, id_);
        float Pb = gw2 * (rr * rr + ii * ii);
        pw[f + 128] = Pb;
        pdl[f + 128] = gw2 * (rd * rd + id_ * id_);
        lmax = fmaxf(Pa, Pb);
    }

    // bin 256: sum (-1)^n h[n] x[n]
    float rr6 = 0.f, rd6 = 0.f;
    for (int q = tid; q < 512; q += 128) {
        float hw = 0.5f - 0.5f * cospif((float)q * (1.f / 256.f));
        if (q & 1) hw = -hw;
        rr6 = fmaf(hw, xr[q], rr6);
        rd6 = fmaf(hw, xd[q], rd6);
    }
#pragma unroll
    for (int o = 16; o > 0; o >>= 1) {
        lmax = fmaxf(lmax, __shfl_xor_sync(0xFFFFFFFFu, lmax, o));
        rr6 += __shfl_xor_sync(0xFFFFFFFFu, rr6, o);
        rd6 += __shfl_xor_sync(0xFFFFFFFFu, rd6, o);
    }
    if (l == 0) { r1[w] = lmax; r2[w] = rr6; r3[w] = rd6; }
    __syncthreads();

    // ---- pmax contribution + grid barrier (one wave; spin is safe) ----
    if (tid == 0) {
        float rra = r2[0] + r2[1] + r2[2] + r2[3];
        float rda = r3[0] + r3[1] + r3[2] + r3[3];
        float P6 = gw2 * rra * rra;
        pw[256]  = P6;
        pdl[256] = gw2 * rda * rda;
        float mx = fmaxf(fmaxf(r1[0], r1[1]), fmaxf(r1[2], r1[3]));
        mx = fmaxf(mx, P6);
        atomicMax(&g_ctl.pmax, __float_as_uint(mx));
        __threadfence();
        atomicAdd(&g_ctl.done, 1u);
        unsigned v;
        do {
            asm volatile("ld.acquire.gpu.u32 %0, [%1];" : "=r"(v) : "l"(&g_ctl.done));
            if (v < (unsigned)T) __nanosleep(256);
        } while (v < (unsigned)T);
        unsigned pmu;
        asm volatile("ld.global.cg.u32 %0, [%1];" : "=r"(pmu) : "l"(&g_ctl.pmax));
        float Pmax = fmaxf(__uint_as_float(pmu), 1e-20f);
        sSC = ex2(31.890509711463527f - lg2(Pmax));   // 10^9.6 / Pmax
    }
    __syncthreads();
    float SC = sSC;

    // ---- phase 2: threshold + loss (all operands in smem) ----
    for (int ff = tid; ff < F; ff += 128) {
        sb[ff]  = g_bark[ff];
        ath[ff] = g_athpow[ff];
        pw[ff]  = SC * fmaxf(pw[ff], 1e-20f);
    }
    keepf[tid] = 1;
    mark[tid] = 0; mark[tid + 128] = 0;
    if (tid == 0) { mark[256] = 0; mark[257] = 0; }
    __syncthreads();

    // per-CTA lim (list positions 0..127) and bstart (all bins), binary search
    if (tid < 128) {
        float hv = sb[tid] + 0.5f;
        int lo = tid, hi = F;
        while (lo + 1 < hi) { int mm = (lo + hi) >> 1; if (sb[mm] < hv) lo = mm; else hi = mm; }
        slim[tid] = (short)lo;
    }
    for (int ff = tid; ff < F; ff += 128) {
        float lv = sb[ff] - 8.f;
        int lo = 0, hi = ff;
        while (lo < hi) { int mm = (lo + hi) >> 1; if (sb[mm] < lv) lo = mm + 1; else hi = mm; }
        sbs[ff] = (short)lo;
    }

    // local-max + ATH candidates
    float p3A = 0.f, p3B = 0.f;
    bool  vA = false, vB = false;
    if (tid >= 1) {
        float a = pw[tid - 1], b = pw[tid], c = pw[tid + 1];
        p3A = a + b + c;
        vA = (b > a) && (b > c) && (p3A > ath[tid]);
    }
    {
        int ff = tid + 128;
        float a = pw[ff - 1], b = pw[ff], c = pw[ff + 1];
        p3B = a + b + c;
        vB = (b > a) && (b > c) && (p3B > ath[ff]);
    }
    unsigned mA = __ballot_sync(0xFFFFFFFFu, vA);
    unsigned mB = __ballot_sync(0xFFFFFFFFu, vB);
    if (l == 0) { cnt[w] = __popc(mA); cnt[4 + w] = __popc(mB); }
    __syncthreads();
    if (tid == 0) {
        int s = 0;
        for (int c = 0; c < 8; c++) { cbase[c] = s; s += cnt[c]; }
        nsh = s;
    }
    __syncthreads();
    unsigned below = (1u << l) - 1u;
    if (vA) {
        int pos = cbase[w] + __popc(mA & below);
        order[pos] = (short)tid;
        mcv[pos]   = DB2 * lg2(p3A);
    }
    if (vB) {
        int pos = cbase[4 + w] + __popc(mB & below);
        order[pos] = (short)(tid + 128);
        mcv[pos]   = DB2 * lg2(p3B);
    }
    __syncthreads();

    // faithful sequential dedup (bark by LIST POSITION via slim[] table)
    if (tid == 0) {
        int n = nsh;
        if (n > 1) {
            int ip = 0, lp = slim[0];
            float mip = mcv[0];
            float mi_next = mcv[1];
            for (int i = 1; i < n; i++) {
                float mi = mi_next;
                if (i + 1 < n) mi_next = mcv[i + 1];
                if (i <= lp) {                 // close
                    if (mip < mi) {
                        keepf[ip] = 0;
                        ip++;
                        mip = mcv[ip];
                        lp  = slim[ip];
                    } else {
                        keepf[i] = 0;
                    }
                } else {
                    ip = i; mip = mi; lp = slim[i];
                }
            }
        }
    }
    __syncthreads();

    // warp 0: compact kept maskers, mark bins, parallel suffix sums (double)
    if (tid < 32) {
        int n = nsh, basep = 0;
        for (int c0 = 0; c0 < n; c0 += 32) {
            int i = c0 + tid;
            bool ok = (i < n) && keepf[i];
            unsigned mm = __ballot_sync(0xFFFFFFFFu, ok);
            if (ok) {
                int pos = basep + __popc(mm & ((1u << tid) - 1u));
                int o = order[i];
                float mv = mcv[i];
                mark[o]  = 1;
                msk[pos] = make_float4(sb[o], (mv + g_dshift[o]) * LG,
                                       fmaf(0.37f, fmaxf(mv - 40.f, 0.f), -27.f) * LG,
                                       0.f);
            }
            basep += __popc(mm);
        }
        int K = basep;
        if (tid == 0) Ksh = K;
        double carry = 0.0;
        if (K > 0) {
            for (int c0 = ((K - 1) >> 5) << 5; c0 >= 0; c0 -= 32) {
                int idx = c0 + tid;
                double p = 0.0;
                if (idx < K) {
                    float4 m4 = msk[idx];
                    float e = fmaf(-SLP, m4.x, m4.y);
                    float ei = floorf(e);
                    p = scalbn((double)ex2(e - ei), (int)ei);
                }
#pragma unroll
                for (int o = 1; o < 32; o <<= 1) {
                    double v = __shfl_down_sync(0xFFFFFFFFu, p, o);
                    if (tid + o < 32) p += v;
                }
                p += carry;
                if (idx < K) {
                    int ex; double mant = frexp(p, &ex);
                    um[idx] = make_float2((float)mant, (float)ex);
                }
                carry = __shfl_sync(0xFFFFFFFFu, p, 0);
            }
        }
        if (tid == 0) um[K] = make_float2(0.f, -1e30f);
    }
    __syncthreads();

    // exclusive prefix count of masker bins -> cum[f]
    {
        int v0 = mark[2 * tid], v1 = mark[2 * tid + 1];
        int s2 = v0 + v1;
        int incl = s2;
#pragma unroll
        for (int o = 1; o < 32; o <<= 1) {
            int u = __shfl_up_sync(0xFFFFFFFFu, incl, o);
            if (l >= o) incl += u;
        }
        if (l == 31) cnt[w] = incl;
        __syncthreads();
        if (tid == 0) {
            int b = 0;
            for (int c = 0; c < 4; c++) { cbase[c] = b; b += cnt[c]; }
        }
        __syncthreads();
        int excl = cbase[w] + incl - s2;
        cum[2 * tid]     = (short)excl;
        cum[2 * tid + 1] = (short)(excl + v0);
        if (tid == 0) cum[256] = (short)Ksh;
    }
    __syncthreads();

    float lsum = 0.f;
    for (int ff = tid; ff < F; ff += 128) {
        float bf = sb[ff];
        int j0 = cum[ff];
        int ks = cum[sbs[ff]];       // maskers >8 bark below: negligible, skip
        float sum = ath[ff];
        for (int kk = ks; kk < j0; kk++) {
            float4 m4 = msk[kk];
            sum += ex2(fmaf(m4.z, bf - m4.x, m4.y));
        }
        float2 u = um[j0];
        sum += u.x * ex2(fmaf(SLP, bf, u.y));
        float v = fmaf(SC, pdl[ff], -sum);
        if (v > 0.f) lsum += v;
    }
#pragma unroll
    for (int o = 16; o > 0; o >>= 1)
        lsum += __shfl_xor_sync(0xFFFFFFFFu, lsum, o);
    if (l == 0) r1[w] = lsum;
    __syncthreads();
    if (tid == 0) {
        g_lpart[t] = r1[0] + r1[1] + r1[2] + r1[3];
        __threadfence();
        unsigned d = atomicAdd(&g_ctl.done2, 1u);
        slast = (d == (unsigned)(T - 1)) ? 1 : 0;
    }
    __syncthreads();
    if (slast) {
        __threadfence();
        double local = 0.0;
        for (int i = tid; i < T; i += 128) local += (double)g_lpart[i];
#pragma unroll
        for (int o = 16; o > 0; o >>= 1)
            local += __shfl_xor_sync(0xFFFFFFFFu, local, o);
        if (l == 0) dred[w] = local;
        __syncthreads();
        if (tid == 0) {
            double acc = dred[0] + dred[1] + dred[2] + dred[3];
            out[0] = (float)(1e-6 * acc / (double)N);
            // self-reset for next graph replay
            g_ctl.pmax = 0u; g_ctl.done = 0u; g_ctl.done2 = 0u;
        }
    }
}

// ---------------------------------------------------------------------------
extern "C" void kernel_launch(void* const* d_in, const int* in_sizes, int n_in,
                              void* d_out, int out_size)
{
    const float* xadv = (const float*)d_in[0];
    const float* xref = (const float*)d_in[1];
    float* out = (float*)d_out;

    int L = in_sizes[0];
    int T = (L - W) / HOP + 1;
    if (T > MAXT) T = MAXT;
    int N = T * F;

    fused_kernel<<<T, 128>>>(out, xadv, xref, T, N);
}

// round 15
// speedup vs baseline: 1.2811x; 1.2811x over previous
#include <cuda_runtime.h>
#include <math.h>

#define W 512
#define F 257
#define HOP 128
#define MAXT 1300

typedef unsigned long long ull;
#define SGNM 0x8000000080000000ULL

__device__ __forceinline__ float ex2(float x) {
    float r; asm("ex2.approx.ftz.f32 %0, %1;" : "=f"(r) : "f"(x)); return r;
}
__device__ __forceinline__ float lg2(float x) {
    float r; asm("lg2.approx.ftz.f32 %0, %1;" : "=f"(r) : "f"(x)); return r;
}
__device__ __forceinline__ ull pack2(float lo, float hi) {
    ull r; asm("mov.b64 %0, {%1, %2};" : "=l"(r) : "f"(lo), "f"(hi)); return r;
}
__device__ __forceinline__ void unpack2(ull v, float &lo, float &hi) {
    asm("mov.b64 {%0, %1}, %2;" : "=f"(lo), "=f"(hi) : "l"(v));
}
__device__ __forceinline__ void ffma2(ull &acc, ull a, ull b) {
    asm("fma.rn.f32x2 %0, %1, %2, %0;" : "+l"(acc) : "l"(a), "l"(b));
}
__device__ __forceinline__ ull mul2(ull a, ull b) {
    ull r; asm("mul.rn.f32x2 %0, %1, %2;" : "=l"(r) : "l"(a), "l"(b)); return r;
}

// ---- static device scratch (zero-init; self-resetting each run) ----
struct Ctl { unsigned int pmax; unsigned int done; unsigned int done2; };
__device__ Ctl   g_ctl;
__device__ float g_lpart[MAXT];
__device__ float g_bark[F], g_dshift[F], g_athpow[F];

// ---------------------------------------------------------------------------
// Fully fused, table-free twiddles: per-CTA frame DFT with register-resident
// twiddle rotation (re-anchored every 16 steps) -> grid spin barrier (one
// wave) -> threshold+loss -> last-CTA finalize.
// ---------------------------------------------------------------------------
__global__ void __launch_bounds__(128, 9) fused_kernel(
    float* __restrict__ out,
    const float* __restrict__ xadv, const float* __restrict__ xref,
    int T, int N)
{
    __shared__ __align__(16) char smbuf[10272];
    // phase-1 views
    float* xr = (float*)(smbuf);                        // [512]
    float* xd = (float*)(smbuf + 2048);                 // [512]
    ulonglong2* eoE = (ulonglong2*)(smbuf + 4096);      // [128]
    ulonglong2* eoO = (ulonglong2*)(smbuf + 6144);      // [128]
    float* pw  = (float*)(smbuf + 8192);                // [257] Pr -> scaled
    float* pdl = (float*)(smbuf + 9232);                // [257] delta power
    // phase-2 overlay over [0, 8192) (written only after the grid barrier)
    float4* msk = (float4*)(smbuf);                     // [128]
    float2* um  = (float2*)(smbuf + 2048);              // [129]
    float*  mcv = (float*)(smbuf + 3088);               // [128]
    short*  order = (short*)(smbuf + 3600);             // [128]
    short*  slim  = (short*)(smbuf + 3856);             // [128]
    short*  sbs   = (short*)(smbuf + 4112);             // [257]
    short*  cum   = (short*)(smbuf + 4632);             // [257]
    unsigned char* mark  = (unsigned char*)(smbuf + 5152);  // [258]
    unsigned char* keepf = (unsigned char*)(smbuf + 5416);  // [128]
    float* sb  = (float*)(smbuf + 5552);                // [257]
    float* ath = (float*)(smbuf + 6592);                // [257]

    __shared__ float  edge[6];
    __shared__ float  r1[4], r2[4], r3[4];
    __shared__ double dred[4];
    __shared__ int    cnt[8], cbase[8];
    __shared__ int    nsh, Ksh, slast;
    __shared__ float  sSC;

    const float LG  = 0.33219280948873623f;   // 0.1*log2(10)
    const float SLP = 27.f * LG;
    const float DB2 = 3.0102999566398120f;    // 10/log2(10)
    const float gw2 = 1.0172526041666667e-5f; // (8/3)/512^2

    int tid = threadIdx.x;
    int w = tid >> 5, l = tid & 31;
    int t = blockIdx.x;
    int base = t * HOP;

    // ---- phase 1: load frame + scattered constant tables ----
    for (int i = tid; i < 512; i += 128) {
        float r = xref[base + i], a = xadv[base + i];
        xr[i] = r; xd[i] = a - r;
    }
    if (t < F && tid == 0) {
        double freq = (double)t * (8000.0 / 256.0);
        double bark = 13.0 * atan(0.00076 * freq)
                    + 3.5  * atan((freq / 7500.0) * (freq / 7500.0));
        float bf = (float)bark;
        g_bark[t]   = bf;
        g_dshift[t] = -6.025f - 0.275f * bf;
        float ap = 0.f;
        if (freq >= 20.0 && freq <= 20000.0) {
            double fk = freq * 0.001;
            double a = 3.64 * pow(fk, -0.8)
                     - 6.5  * exp(-0.6 * (fk - 3.3) * (fk - 3.3))
                     + 0.001 * fk * fk * fk * fk - 12.0;
            ap = exp10f((float)a * 0.1f);
        }
        g_athpow[t] = ap;
    }
    __syncthreads();

    // eo build (n = tid)
    {
        int n = tid;
        if (n == 0) {
            edge[0] = xr[256];
            edge[1] = (xr[128] + xr[384]) * 0.5f;
            edge[2] = (xr[128] - xr[384]) * 0.5f;
            edge[3] = xd[256];
            edge[4] = (xd[128] + xd[384]) * 0.5f;
            edge[5] = (xd[128] - xd[384]) * 0.5f;
        } else {
            float h1 = 0.5f - 0.5f * cospif((float)n * (1.f / 256.f));
            float h2 = 0.5f - 0.5f * cospif((float)(256 - n) * (1.f / 256.f));
            float a1 = xr[n], a2 = xr[512 - n], a3 = xr[256 - n], a4 = xr[256 + n];
            float b1 = xd[n], b2 = xd[512 - n], b3 = xd[256 - n], b4 = xd[256 + n];
            float p1r = (a1 + a2) * h1, p2r = (a3 + a4) * h2;
            float q1r = (a1 - a2) * h1, q2r = (a3 - a4) * h2;
            float p1d = (b1 + b2) * h1, p2d = (b3 + b4) * h2;
            float q1d = (b1 - b2) * h1, q2d = (b3 - b4) * h2;
            ulonglong2 ue, uo;
            ue.x = pack2(p1r + p2r, p1d + p2d);
            ue.y = pack2(q1r - q2r, q1d - q2d);
            uo.x = pack2(p1r - p2r, p1d - p2d);
            uo.y = pack2(q1r + q2r, q1d + q2d);
            eoE[n] = ue; eoO[n] = uo;
        }
    }
    __syncthreads();

    // DFT: thread handles bins f = 2m+par and f+128 (rotation trick).
    // Twiddles live in registers: tw(n+1) = tw(n) * e^{i*2*pi*f/512},
    // re-anchored exactly every 16 steps via sincospif.
    int m = tid & 63, par = tid >> 6;
    int f = 2 * m + par;
    float sgn = (m & 1) ? -1.f : 1.f;
    const ulonglong2* eo = par ? eoO : eoE;

    ull aR, aI, bR, bI;
    if (par == 0) {
        aR = pack2(fmaf(sgn, edge[1], edge[0]), fmaf(sgn, edge[4], edge[3]));
        aI = 0; bR = aR; bI = 0;
    } else {
        aR = pack2(-edge[0], -edge[3]);
        aI = pack2(sgn * edge[2], sgn * edge[5]);
        bR = aR; bI = aI;
    }

    float cf, sf;
    sincospif((float)f * (1.f / 256.f), &sf, &cf);
    ull rotC = pack2(cf, cf), rotS = pack2(sf, sf);
    ull rotSn = rotS ^ SGNM;
    ull cc = rotC, ss = rotS;            // twiddle at n = 1

#define STEP(RMODE) {                                                  \
        ulonglong2 v = eo[n];                                          \
        ffma2(aR, v.x, cc); ffma2(aI, v.y, ss);                        \
        if (RMODE == 0) { ffma2(bR, v.x, cc);        ffma2(bI, v.y, ss); }        \
        if (RMODE == 1) { ffma2(bR, v.x, ss ^ SGNM); ffma2(bI, v.y, cc); }        \
        if (RMODE == 2) { ffma2(bR, v.x, cc ^ SGNM); ffma2(bI, v.y, ss ^ SGNM); } \
        if (RMODE == 3) { ffma2(bR, v.x, ss);        ffma2(bI, v.y, cc ^ SGNM); } \
        ull ncc = mul2(cc, rotC); ffma2(ncc, ss, rotSn);               \
        ull nss = mul2(ss, rotC); ffma2(nss, cc, rotS);                \
        cc = ncc; ss = nss; n++; }

    int n = 1;
#pragma unroll 1
    for (int blk = 0; blk < 8; blk++) {
        if (blk) {                       // exact re-anchor at n = 16*blk + 1
            int kk = (n * f) & 511;
            float s2, c2;
            sincospif((float)kk * (1.f / 256.f), &s2, &c2);
            cc = pack2(c2, c2); ss = pack2(s2, s2);
        }
        if (blk < 7) {
#pragma unroll
            for (int q = 0; q < 4; q++) { STEP(1) STEP(2) STEP(3) STEP(0) }
        } else {
#pragma unroll
            for (int q = 0; q < 3; q++) { STEP(1) STEP(2) STEP(3) STEP(0) }
            STEP(1) STEP(2) STEP(3)
        }
    }
#undef STEP

    float lmax;
    {
        float rr, rd, ii, id_;
        unpack2(aR, rr, rd); unpack2(aI, ii, id_);
        float Pa = gw2 * (rr * rr + ii * ii);
        pw[f] = Pa;
        pdl[f] = gw2 * (rd * rd + id_ * id_);
        unpack2(bR, rr, rd); unpack2(bI, ii, id_);
        float Pb = gw2 * (rr * rr + ii * ii);
        pw[f + 128] = Pb;
        pdl[f + 128] = gw2 * (rd * rd + id_ * id_);
        lmax = fmaxf(Pa, Pb);
    }

    // bin 256: sum (-1)^n h[n] x[n]
    float rr6 = 0.f, rd6 = 0.f;
    for (int q = tid; q < 512; q += 128) {
        float hw = 0.5f - 0.5f * cospif((float)q * (1.f / 256.f));
        if (q & 1) hw = -hw;
        rr6 = fmaf(hw, xr[q], rr6);
        rd6 = fmaf(hw, xd[q], rd6);
    }
#pragma unroll
    for (int o = 16; o > 0; o >>= 1) {
        lmax = fmaxf(lmax, __shfl_xor_sync(0xFFFFFFFFu, lmax, o));
        rr6 += __shfl_xor_sync(0xFFFFFFFFu, rr6, o);
        rd6 += __shfl_xor_sync(0xFFFFFFFFu, rd6, o);
    }
    if (l == 0) { r1[w] = lmax; r2[w] = rr6; r3[w] = rd6; }
    __syncthreads();

    // ---- pmax contribution + grid barrier (one wave; spin is safe) ----
    if (tid == 0) {
        float rra = r2[0] + r2[1] + r2[2] + r2[3];
        float rda = r3[0] + r3[1] + r3[2] + r3[3];
        float P6 = gw2 * rra * rra;
        pw[256]  = P6;
        pdl[256] = gw2 * rda * rda;
        float mx = fmaxf(fmaxf(r1[0], r1[1]), fmaxf(r1[2], r1[3]));
        mx = fmaxf(mx, P6);
        atomicMax(&g_ctl.pmax, __float_as_uint(mx));
        __threadfence();
        atomicAdd(&g_ctl.done, 1u);
        unsigned v;
        do {
            asm volatile("ld.acquire.gpu.u32 %0, [%1];" : "=r"(v) : "l"(&g_ctl.done));
            if (v < (unsigned)T) __nanosleep(256);
        } while (v < (unsigned)T);
        unsigned pmu;
        asm volatile("ld.global.cg.u32 %0, [%1];" : "=r"(pmu) : "l"(&g_ctl.pmax));
        float Pmax = fmaxf(__uint_as_float(pmu), 1e-20f);
        sSC = ex2(31.890509711463527f - lg2(Pmax));   // 10^9.6 / Pmax
    }
    __syncthreads();
    float SC = sSC;

    // ---- phase 2: threshold + loss (all operands in smem) ----
    for (int ff = tid; ff < F; ff += 128) {
        sb[ff]  = g_bark[ff];
        ath[ff] = g_athpow[ff];
        pw[ff]  = SC * fmaxf(pw[ff], 1e-20f);
    }
    keepf[tid] = 1;
    mark[tid] = 0; mark[tid + 128] = 0;
    if (tid == 0) { mark[256] = 0; mark[257] = 0; }
    __syncthreads();

    // per-CTA lim (list positions 0..127) and bstart (all bins), binary search
    if (tid < 128) {
        float hv = sb[tid] + 0.5f;
        int lo = tid, hi = F;
        while (lo + 1 < hi) { int mm = (lo + hi) >> 1; if (sb[mm] < hv) lo = mm; else hi = mm; }
        slim[tid] = (short)lo;
    }
    for (int ff = tid; ff < F; ff += 128) {
        float lv = sb[ff] - 8.f;
        int lo = 0, hi = ff;
        while (lo < hi) { int mm = (lo + hi) >> 1; if (sb[mm] < lv) lo = mm + 1; else hi = mm; }
        sbs[ff] = (short)lo;
    }

    // local-max + ATH candidates
    float p3A = 0.f, p3B = 0.f;
    bool  vA = false, vB = false;
    if (tid >= 1) {
        float a = pw[tid - 1], b = pw[tid], c = pw[tid + 1];
        p3A = a + b + c;
        vA = (b > a) && (b > c) && (p3A > ath[tid]);
    }
    {
        int ff = tid + 128;
        float a = pw[ff - 1], b = pw[ff], c = pw[ff + 1];
        p3B = a + b + c;
        vB = (b > a) && (b > c) && (p3B > ath[ff]);
    }
    unsigned mA = __ballot_sync(0xFFFFFFFFu, vA);
    unsigned mB = __ballot_sync(0xFFFFFFFFu, vB);
    if (l == 0) { cnt[w] = __popc(mA); cnt[4 + w] = __popc(mB); }
    __syncthreads();
    if (tid == 0) {
        int s = 0;
        for (int c = 0; c < 8; c++) { cbase[c] = s; s += cnt[c]; }
        nsh = s;
    }
    __syncthreads();
    unsigned below = (1u << l) - 1u;
    if (vA) {
        int pos = cbase[w] + __popc(mA & below);
        order[pos] = (short)tid;
        mcv[pos]   = DB2 * lg2(p3A);
    }
    if (vB) {
        int pos = cbase[4 + w] + __popc(mB & below);
        order[pos] = (short)(tid + 128);
        mcv[pos]   = DB2 * lg2(p3B);
    }
    __syncthreads();

    // faithful sequential dedup (bark by LIST POSITION via slim[] table)
    if (tid == 0) {
        int n2 = nsh;
        if (n2 > 1) {
            int ip = 0, lp = slim[0];
            float mip = mcv[0];
            float mi_next = mcv[1];
            for (int i = 1; i < n2; i++) {
                float mi = mi_next;
                if (i + 1 < n2) mi_next = mcv[i + 1];
                if (i <= lp) {                 // close
                    if (mip < mi) {
                        keepf[ip] = 0;
                        ip++;
                        mip = mcv[ip];
                        lp  = slim[ip];
                    } else {
                        keepf[i] = 0;
                    }
                } else {
                    ip = i; mip = mi; lp = slim[i];
                }
            }
        }
    }
    __syncthreads();

    // warp 0: compact kept maskers, mark bins, parallel suffix sums (double)
    if (tid < 32) {
        int n2 = nsh, basep = 0;
        for (int c0 = 0; c0 < n2; c0 += 32) {
            int i = c0 + tid;
            bool ok = (i < n2) && keepf[i];
            unsigned mm = __ballot_sync(0xFFFFFFFFu, ok);
            if (ok) {
                int pos = basep + __popc(mm & ((1u << tid) - 1u));
                int o = order[i];
                float mv = mcv[i];
                mark[o]  = 1;
                msk[pos] = make_float4(sb[o], (mv + g_dshift[o]) * LG,
                                       fmaf(0.37f, fmaxf(mv - 40.f, 0.f), -27.f) * LG,
                                       0.f);
            }
            basep += __popc(mm);
        }
        int K = basep;
        if (tid == 0) Ksh = K;
        double carry = 0.0;
        if (K > 0) {
            for (int c0 = ((K - 1) >> 5) << 5; c0 >= 0; c0 -= 32) {
                int idx = c0 + tid;
                double p = 0.0;
                if (idx < K) {
                    float4 m4 = msk[idx];
                    float e = fmaf(-SLP, m4.x, m4.y);
                    float ei = floorf(e);
                    p = scalbn((double)ex2(e - ei), (int)ei);
                }
#pragma unroll
                for (int o = 1; o < 32; o <<= 1) {
                    double v = __shfl_down_sync(0xFFFFFFFFu, p, o);
                    if (tid + o < 32) p += v;
                }
                p += carry;
                if (idx < K) {
                    int ex; double mant = frexp(p, &ex);
                    um[idx] = make_float2((float)mant, (float)ex);
                }
                carry = __shfl_sync(0xFFFFFFFFu, p, 0);
            }
        }
        if (tid == 0) um[K] = make_float2(0.f, -1e30f);
    }
    __syncthreads();

    // exclusive prefix count of masker bins -> cum[f]
    {
        int v0 = mark[2 * tid], v1 = mark[2 * tid + 1];
        int s2 = v0 + v1;
        int incl = s2;
#pragma unroll
        for (int o = 1; o < 32; o <<= 1) {
            int u = __shfl_up_sync(0xFFFFFFFFu, incl, o);
            if (l >= o) incl += u;
        }
        if (l == 31) cnt[w] = incl;
        __syncthreads();
        if (tid == 0) {
            int b = 0;
            for (int c = 0; c < 4; c++) { cbase[c] = b; b += cnt[c]; }
        }
        __syncthreads();
        int excl = cbase[w] + incl - s2;
        cum[2 * tid]     = (short)excl;
        cum[2 * tid + 1] = (short)(excl + v0);
        if (tid == 0) cum[256] = (short)Ksh;
    }
    __syncthreads();

    float lsum = 0.f;
    for (int ff = tid; ff < F; ff += 128) {
        float bf = sb[ff];
        int j0 = cum[ff];
        int ks = cum[sbs[ff]];       // maskers >8 bark below: negligible, skip
        float sum = ath[ff];
        for (int kk = ks; kk < j0; kk++) {
            float4 m4 = msk[kk];
            sum += ex2(fmaf(m4.z, bf - m4.x, m4.y));
        }
        float2 u = um[j0];
        sum += u.x * ex2(fmaf(SLP, bf, u.y));
        float v = fmaf(SC, pdl[ff], -sum);
        if (v > 0.f) lsum += v;
    }
#pragma unroll
    for (int o = 16; o > 0; o >>= 1)
        lsum += __shfl_xor_sync(0xFFFFFFFFu, lsum, o);
    if (l == 0) r1[w] = lsum;
    __syncthreads();
    if (tid == 0) {
        g_lpart[t] = r1[0] + r1[1] + r1[2] + r1[3];
        __threadfence();
        unsigned d = atomicAdd(&g_ctl.done2, 1u);
        slast = (d == (unsigned)(T - 1)) ? 1 : 0;
    }
    __syncthreads();
    if (slast) {
        __threadfence();
        double local = 0.0;
        for (int i = tid; i < T; i += 128) local += (double)g_lpart[i];
#pragma unroll
        for (int o = 16; o > 0; o >>= 1)
            local += __shfl_xor_sync(0xFFFFFFFFu, local, o);
        if (l == 0) dred[w] = local;
        __syncthreads();
        if (tid == 0) {
            double acc = dred[0] + dred[1] + dred[2] + dred[3];
            out[0] = (float)(1e-6 * acc / (double)N);
            // self-reset for next graph replay
            g_ctl.pmax = 0u; g_ctl.done = 0u; g_ctl.done2 = 0u;
        }
    }
}

// ---------------------------------------------------------------------------
extern "C" void kernel_launch(void* const* d_in, const int* in_sizes, int n_in,
                              void* d_out, int out_size)
{
    const float* xadv = (const float*)d_in[0];
    const float* xref = (const float*)d_in[1];
    float* out = (float*)d_out;

    int L = in_sizes[0];
    int T = (L - W) / HOP + 1;
    if (T > MAXT) T = MAXT;
    int N = T * F;

    fused_kernel<<<T, 128>>>(out, xadv, xref, T, N);
}

// round 16
// speedup vs baseline: 1.5950x; 1.2451x over previous
#include <cuda_runtime.h>
#include <math.h>

#define W 512
#define F 257
#define HOP 128
#define MAXT 1300

__device__ __forceinline__ float ex2(float x) {
    float r; asm("ex2.approx.ftz.f32 %0, %1;" : "=f"(r) : "f"(x)); return r;
}
__device__ __forceinline__ float lg2(float x) {
    float r; asm("lg2.approx.ftz.f32 %0, %1;" : "=f"(r) : "f"(x)); return r;
}

// ---- static device scratch (zero-init; self-resetting each run) ----
struct Ctl { unsigned int pmax; unsigned int done; unsigned int done2; };
__device__ Ctl   g_ctl;
__device__ float g_lpart[MAXT];
__device__ float g_bark[F], g_dshift[F], g_athpow[F];

// ---------------------------------------------------------------------------
// Fully fused: per-CTA 512-pt radix-2 DIF FFT (ref+delta packed as complex)
// -> conjugate-symmetry separation -> grid spin barrier (one wave) ->
// threshold+loss -> last-CTA finalize.
// ---------------------------------------------------------------------------
__global__ void __launch_bounds__(128, 9) fused_kernel(
    float* __restrict__ out,
    const float* __restrict__ xadv, const float* __restrict__ xref,
    int T, int N)
{
    __shared__ __align__(16) char smbuf[9696];
    // phase-1 views (FFT workspace; overlapped by phase-2 overlay)
    float* re = (float*)(smbuf);                        // [512]
    float* im = (float*)(smbuf + 2048);                 // [512]
    // persistent across barrier
    float* pw  = (float*)(smbuf + 7632);                // [257]
    float* pdl = (float*)(smbuf + 8660);                // [257]
    // phase-2 overlay over [0, 7620) (written only after the grid barrier)
    float4* msk = (float4*)(smbuf);                     // [128]
    float2* um  = (float2*)(smbuf + 2048);              // [129]
    float*  mcv = (float*)(smbuf + 3088);               // [128]
    short*  order = (short*)(smbuf + 3600);             // [128]
    short*  slim  = (short*)(smbuf + 3856);             // [128]
    short*  sbs   = (short*)(smbuf + 4112);             // [257]
    short*  cum   = (short*)(smbuf + 4632);             // [257]
    unsigned char* mark  = (unsigned char*)(smbuf + 5152);  // [258]
    unsigned char* keepf = (unsigned char*)(smbuf + 5416);  // [128]
    float* sb  = (float*)(smbuf + 5552);                // [257]
    float* ath = (float*)(smbuf + 6592);                // [257]

    __shared__ float  r1[4];
    __shared__ double dred[4];
    __shared__ int    cnt[8], cbase[8];
    __shared__ int    nsh, Ksh, slast;
    __shared__ float  sSC;

    const float LG  = 0.33219280948873623f;   // 0.1*log2(10)
    const float SLP = 27.f * LG;
    const float DB2 = 3.0102999566398120f;    // 10/log2(10)
    const float gw2q = 1.0172526041666667e-5f * 0.25f; // (8/3)/512^2 / 4

    int tid = threadIdx.x;
    int w = tid >> 5, l = tid & 31;
    int t = blockIdx.x;
    int base = t * HOP;

    // ---- phase 1: load + window (packed complex) + scattered tables ----
    for (int i = tid; i < 512; i += 128) {
        float r = xref[base + i], a = xadv[base + i];
        float h = 0.5f - 0.5f * cospif((float)i * (1.f / 256.f));
        re[i] = h * r;
        im[i] = h * (a - r);
    }
    if (t < F && tid == 0) {
        double freq = (double)t * (8000.0 / 256.0);
        double bark = 13.0 * atan(0.00076 * freq)
                    + 3.5  * atan((freq / 7500.0) * (freq / 7500.0));
        float bf = (float)bark;
        g_bark[t]   = bf;
        g_dshift[t] = -6.025f - 0.275f * bf;
        float ap = 0.f;
        if (freq >= 20.0 && freq <= 20000.0) {
            double fk = freq * 0.001;
            double a = 3.64 * pow(fk, -0.8)
                     - 6.5  * exp(-0.6 * (fk - 3.3) * (fk - 3.3))
                     + 0.001 * fk * fk * fk * fk - 12.0;
            ap = exp10f((float)a * 0.1f);
        }
        g_athpow[t] = ap;
    }
    __syncthreads();

    // ---- 512-pt radix-2 DIF FFT (9 stages), output bit-reversed ----
#pragma unroll
    for (int s = 0; s < 9; s++) {
        const int d = 256 >> s;
        const float invd = -1.f / (float)d;
#pragma unroll
        for (int h2 = 0; h2 < 2; h2++) {
            int q = tid + h2 * 128;
            int j = q & (d - 1);
            int bse = ((q & ~(d - 1)) << 1) | j;
            float ar = re[bse],     ai = im[bse];
            float br = re[bse + d], bi = im[bse + d];
            float ts, tc;
            sincospif((float)j * invd, &ts, &tc);   // e^{-i*pi*j/d}
            re[bse] = ar + br;  im[bse] = ai + bi;
            float sr = ar - br, si = ai - bi;
            re[bse + d] = sr * tc - si * ts;
            im[bse + d] = sr * ts + si * tc;
        }
        __syncthreads();
    }

    // ---- separate ref/delta spectra, powers, local max ----
    float lmax;
    {
        float lm = 0.f;
#pragma unroll
        for (int h2 = 0; h2 < 3; h2++) {
            int k = (h2 < 2) ? (tid + h2 * 128) : 256;
            if (h2 == 2 && tid != 0) break;
            int i1 = __brev((unsigned)k) >> 23;
            int i2 = __brev((unsigned)((512 - k) & 511)) >> 23;
            float zr = re[i1], zi = im[i1];
            float mr = re[i2], mi = im[i2];
            float Rr = zr + mr, Ri = zi - mi;     // 2*ref spectrum
            float Dr = zi + mi, Di = mr - zr;     // 2*delta spectrum
            float Pa = gw2q * (Rr * Rr + Ri * Ri);
            float Pd = gw2q * (Dr * Dr + Di * Di);
            pw[k] = Pa; pdl[k] = Pd;
            lm = fmaxf(lm, Pa);
        }
        lmax = lm;
    }
#pragma unroll
    for (int o = 16; o > 0; o >>= 1)
        lmax = fmaxf(lmax, __shfl_xor_sync(0xFFFFFFFFu, lmax, o));
    if (l == 0) r1[w] = lmax;
    __syncthreads();

    // ---- pmax contribution + grid barrier (one wave; spin is safe) ----
    if (tid == 0) {
        float mx = fmaxf(fmaxf(r1[0], r1[1]), fmaxf(r1[2], r1[3]));
        atomicMax(&g_ctl.pmax, __float_as_uint(mx));
        __threadfence();
        atomicAdd(&g_ctl.done, 1u);
        unsigned v;
        do {
            asm volatile("ld.acquire.gpu.u32 %0, [%1];" : "=r"(v) : "l"(&g_ctl.done));
            if (v < (unsigned)T) __nanosleep(256);
        } while (v < (unsigned)T);
        unsigned pmu;
        asm volatile("ld.global.cg.u32 %0, [%1];" : "=r"(pmu) : "l"(&g_ctl.pmax));
        float Pmax = fmaxf(__uint_as_float(pmu), 1e-20f);
        sSC = ex2(31.890509711463527f - lg2(Pmax));   // 10^9.6 / Pmax
    }
    __syncthreads();
    float SC = sSC;

    // ---- phase 2: threshold + loss (all operands in smem) ----
    for (int ff = tid; ff < F; ff += 128) {
        sb[ff]  = g_bark[ff];
        ath[ff] = g_athpow[ff];
        pw[ff]  = SC * fmaxf(pw[ff], 1e-20f);
    }
    keepf[tid] = 1;
    mark[tid] = 0; mark[tid + 128] = 0;
    if (tid == 0) { mark[256] = 0; mark[257] = 0; }
    __syncthreads();

    // per-CTA lim (list positions 0..127) and bstart (all bins), binary search
    if (tid < 128) {
        float hv = sb[tid] + 0.5f;
        int lo = tid, hi = F;
        while (lo + 1 < hi) { int mm = (lo + hi) >> 1; if (sb[mm] < hv) lo = mm; else hi = mm; }
        slim[tid] = (short)lo;
    }
    for (int ff = tid; ff < F; ff += 128) {
        float lv = sb[ff] - 8.f;
        int lo = 0, hi = ff;
        while (lo < hi) { int mm = (lo + hi) >> 1; if (sb[mm] < lv) lo = mm + 1; else hi = mm; }
        sbs[ff] = (short)lo;
    }

    // local-max + ATH candidates
    float p3A = 0.f, p3B = 0.f;
    bool  vA = false, vB = false;
    if (tid >= 1) {
        float a = pw[tid - 1], b = pw[tid], c = pw[tid + 1];
        p3A = a + b + c;
        vA = (b > a) && (b > c) && (p3A > ath[tid]);
    }
    {
        int ff = tid + 128;
        float a = pw[ff - 1], b = pw[ff], c = pw[ff + 1];
        p3B = a + b + c;
        vB = (b > a) && (b > c) && (p3B > ath[ff]);
    }
    unsigned mA = __ballot_sync(0xFFFFFFFFu, vA);
    unsigned mB = __ballot_sync(0xFFFFFFFFu, vB);
    if (l == 0) { cnt[w] = __popc(mA); cnt[4 + w] = __popc(mB); }
    __syncthreads();
    if (tid == 0) {
        int s = 0;
        for (int c = 0; c < 8; c++) { cbase[c] = s; s += cnt[c]; }
        nsh = s;
    }
    __syncthreads();
    unsigned below = (1u << l) - 1u;
    if (vA) {
        int pos = cbase[w] + __popc(mA & below);
        order[pos] = (short)tid;
        mcv[pos]   = DB2 * lg2(p3A);
    }
    if (vB) {
        int pos = cbase[4 + w] + __popc(mB & below);
        order[pos] = (short)(tid + 128);
        mcv[pos]   = DB2 * lg2(p3B);
    }
    __syncthreads();

    // faithful sequential dedup (bark by LIST POSITION via slim[] table)
    if (tid == 0) {
        int n2 = nsh;
        if (n2 > 1) {
            int ip = 0, lp = slim[0];
            float mip = mcv[0];
            float mi_next = mcv[1];
            for (int i = 1; i < n2; i++) {
                float mi = mi_next;
                if (i + 1 < n2) mi_next = mcv[i + 1];
                if (i <= lp) {                 // close
                    if (mip < mi) {
                        keepf[ip] = 0;
                        ip++;
                        mip = mcv[ip];
                        lp  = slim[ip];
                    } else {
                        keepf[i] = 0;
                    }
                } else {
                    ip = i; mip = mi; lp = slim[i];
                }
            }
        }
    }
    __syncthreads();

    // warp 0: compact kept maskers, mark bins, parallel suffix sums (double)
    if (tid < 32) {
        int n2 = nsh, basep = 0;
        for (int c0 = 0; c0 < n2; c0 += 32) {
            int i = c0 + tid;
            bool ok = (i < n2) && keepf[i];
            unsigned mm = __ballot_sync(0xFFFFFFFFu, ok);
            if (ok) {
                int pos = basep + __popc(mm & ((1u << tid) - 1u));
                int o = order[i];
                float mv = mcv[i];
                mark[o]  = 1;
                msk[pos] = make_float4(sb[o], (mv + g_dshift[o]) * LG,
                                       fmaf(0.37f, fmaxf(mv - 40.f, 0.f), -27.f) * LG,
                                       0.f);
            }
            basep += __popc(mm);
        }
        int K = basep;
        if (tid == 0) Ksh = K;
        double carry = 0.0;
        if (K > 0) {
            for (int c0 = ((K - 1) >> 5) << 5; c0 >= 0; c0 -= 32) {
                int idx = c0 + tid;
                double p = 0.0;
                if (idx < K) {
                    float4 m4 = msk[idx];
                    float e = fmaf(-SLP, m4.x, m4.y);
                    float ei = floorf(e);
                    p = scalbn((double)ex2(e - ei), (int)ei);
                }
#pragma unroll
                for (int o = 1; o < 32; o <<= 1) {
                    double v = __shfl_down_sync(0xFFFFFFFFu, p, o);
                    if (tid + o < 32) p += v;
                }
                p += carry;
                if (idx < K) {
                    int ex; double mant = frexp(p, &ex);
                    um[idx] = make_float2((float)mant, (float)ex);
                }
                carry = __shfl_sync(0xFFFFFFFFu, p, 0);
            }
        }
        if (tid == 0) um[K] = make_float2(0.f, -1e30f);
    }
    __syncthreads();

    // exclusive prefix count of masker bins -> cum[f]
    {
        int v0 = mark[2 * tid], v1 = mark[2 * tid + 1];
        int s2 = v0 + v1;
        int incl = s2;
#pragma unroll
        for (int o = 1; o < 32; o <<= 1) {
            int u = __shfl_up_sync(0xFFFFFFFFu, incl, o);
            if (l >= o) incl += u;
        }
        if (l == 31) cnt[w] = incl;
        __syncthreads();
        if (tid == 0) {
            int b = 0;
            for (int c = 0; c < 4; c++) { cbase[c] = b; b += cnt[c]; }
        }
        __syncthreads();
        int excl = cbase[w] + incl - s2;
        cum[2 * tid]     = (short)excl;
        cum[2 * tid + 1] = (short)(excl + v0);
        if (tid == 0) cum[256] = (short)Ksh;
    }
    __syncthreads();

    float lsum = 0.f;
    for (int ff = tid; ff < F; ff += 128) {
        float bf = sb[ff];
        int j0 = cum[ff];
        int ks = cum[sbs[ff]];       // maskers >8 bark below: negligible, skip
        float sum = ath[ff];
        for (int kk = ks; kk < j0; kk++) {
            float4 m4 = msk[kk];
            sum += ex2(fmaf(m4.z, bf - m4.x, m4.y));
        }
        float2 u = um[j0];
        sum += u.x * ex2(fmaf(SLP, bf, u.y));
        float v = fmaf(SC, pdl[ff], -sum);
        if (v > 0.f) lsum += v;
    }
#pragma unroll
    for (int o = 16; o > 0; o >>= 1)
        lsum += __shfl_xor_sync(0xFFFFFFFFu, lsum, o);
    if (l == 0) r1[w] = lsum;
    __syncthreads();
    if (tid == 0) {
        g_lpart[t] = r1[0] + r1[1] + r1[2] + r1[3];
        __threadfence();
        unsigned d = atomicAdd(&g_ctl.done2, 1u);
        slast = (d == (unsigned)(T - 1)) ? 1 : 0;
    }
    __syncthreads();
    if (slast) {
        __threadfence();
        double local = 0.0;
        for (int i = tid; i < T; i += 128) local += (double)g_lpart[i];
#pragma unroll
        for (int o = 16; o > 0; o >>= 1)
            local += __shfl_xor_sync(0xFFFFFFFFu, local, o);
        if (l == 0) dred[w] = local;
        __syncthreads();
        if (tid == 0) {
            double acc = dred[0] + dred[1] + dred[2] + dred[3];
            out[0] = (float)(1e-6 * acc / (double)N);
            // self-reset for next graph replay
            g_ctl.pmax = 0u; g_ctl.done = 0u; g_ctl.done2 = 0u;
        }
    }
}

// ---------------------------------------------------------------------------
extern "C" void kernel_launch(void* const* d_in, const int* in_sizes, int n_in,
                              void* d_out, int out_size)
{
    const float* xadv = (const float*)d_in[0];
    const float* xref = (const float*)d_in[1];
    float* out = (float*)d_out;

    int L = in_sizes[0];
    int T = (L - W) / HOP + 1;
    if (T > MAXT) T = MAXT;
    int N = T * F;

    fused_kernel<<<T, 128>>>(out, xadv, xref, T, N);
}

// round 17
// speedup vs baseline: 1.6842x; 1.0559x over previous
#include <cuda_runtime.h>
#include <math.h>

#define W 512
#define F 257
#define HOP 128
#define MAXT 1300
#define PAD(i) ((i) + ((i) >> 5))

__device__ __forceinline__ float ex2(float x) {
    float r; asm("ex2.approx.ftz.f32 %0, %1;" : "=f"(r) : "f"(x)); return r;
}
__device__ __forceinline__ float lg2(float x) {
    float r; asm("lg2.approx.ftz.f32 %0, %1;" : "=f"(r) : "f"(x)); return r;
}

// ---- static device scratch (zero-init; self-resetting each run) ----
struct Ctl { unsigned int pmax; unsigned int done; unsigned int done2; };
__device__ Ctl   g_ctl;
__device__ float g_lpart[MAXT];
__device__ float g_bark[F], g_dshift[F], g_athpow[F];

// ---------------------------------------------------------------------------
// Fully fused: per-CTA 512-pt radix-2^2 FFT (4 fused stage-pairs + 1 radix-2,
// ref+delta packed complex) -> conjugate separation -> grid spin barrier ->
// threshold+loss -> last-CTA finalize.
// ---------------------------------------------------------------------------
__global__ void __launch_bounds__(128, 9) fused_kernel(
    float* __restrict__ out,
    const float* __restrict__ xadv, const float* __restrict__ xref,
    int T, int N)
{
    __shared__ __align__(16) char smbuf[9696];
    // phase-1 views (FFT workspace, padded [528]; overlapped by phase-2)
    float* re = (float*)(smbuf);                        // [528]
    float* im = (float*)(smbuf + 2112);                 // [528]
    // persistent across barrier
    float* pw  = (float*)(smbuf + 7632);                // [257]
    float* pdl = (float*)(smbuf + 8660);                // [257]
    // phase-2 overlay over [0, 7620) (written only after the grid barrier)
    float4* msk = (float4*)(smbuf);                     // [128]
    float2* um  = (float2*)(smbuf + 2048);              // [129]
    float*  mcv = (float*)(smbuf + 3088);               // [128]
    short*  order = (short*)(smbuf + 3600);             // [128]
    short*  slim  = (short*)(smbuf + 3856);             // [128]
    short*  sbs   = (short*)(smbuf + 4112);             // [257]
    short*  cum   = (short*)(smbuf + 4632);             // [257]
    unsigned char* mark  = (unsigned char*)(smbuf + 5152);  // [258]
    unsigned char* keepf = (unsigned char*)(smbuf + 5416);  // [128]
    float* sb  = (float*)(smbuf + 5552);                // [257]
    float* ath = (float*)(smbuf + 6592);                // [257]

    __shared__ float  r1[4];
    __shared__ double dred[4];
    __shared__ int    cnt[8], cbase[8];
    __shared__ int    nsh, Ksh, slast;
    __shared__ float  sSC;

    const float LG  = 0.33219280948873623f;   // 0.1*log2(10)
    const float SLP = 27.f * LG;
    const float DB2 = 3.0102999566398120f;    // 10/log2(10)
    const float gw2q = 1.0172526041666667e-5f * 0.25f; // (8/3)/512^2 / 4

    int tid = threadIdx.x;
    int w = tid >> 5, l = tid & 31;
    int t = blockIdx.x;
    int base = t * HOP;

    // ---- phase 1: load + window (packed complex) + scattered tables ----
    for (int i = tid; i < 512; i += 128) {
        float r = xref[base + i], a = xadv[base + i];
        float h = 0.5f - 0.5f * cospif((float)i * (1.f / 256.f));
        re[PAD(i)] = h * r;
        im[PAD(i)] = h * (a - r);
    }
    if (t < F && tid == 0) {
        double freq = (double)t * (8000.0 / 256.0);
        double bark = 13.0 * atan(0.00076 * freq)
                    + 3.5  * atan((freq / 7500.0) * (freq / 7500.0));
        float bf = (float)bark;
        g_bark[t]   = bf;
        g_dshift[t] = -6.025f - 0.275f * bf;
        float ap = 0.f;
        if (freq >= 20.0 && freq <= 20000.0) {
            double fk = freq * 0.001;
            double a = 3.64 * pow(fk, -0.8)
                     - 6.5  * exp(-0.6 * (fk - 3.3) * (fk - 3.3))
                     + 0.001 * fk * fk * fk * fk - 12.0;
            ap = exp10f((float)a * 0.1f);
        }
        g_athpow[t] = ap;
    }
    __syncthreads();

    // ---- radix-2^2: 4 fused stage-pairs (stages 0..7) ----
#pragma unroll
    for (int p = 0; p < 4; p++) {
        const int d  = 256 >> (2 * p);
        const int e  = d >> 1;
        const int le = 7 - 2 * p;          // log2(e)
        int j1  = tid & (e - 1);
        int blk = tid >> le;
        int i0  = blk * 2 * d + j1;
        int iA = PAD(i0), iB = PAD(i0 + e), iC = PAD(i0 + d), iD = PAD(i0 + d + e);

        float x0r = re[iA], x0i = im[iA];
        float x1r = re[iB], x1i = im[iB];
        float x2r = re[iC], x2i = im[iC];
        float x3r = re[iD], x3i = im[iD];

        float sn, cs;
        sincospif(-(float)j1 / (float)d, &sn, &cs);   // W1 = cs + i*sn
        float w3c = cs * cs - sn * sn;                 // W3 = W1^2
        float w3s = 2.f * cs * sn;

        // stage s
        float a0r = x0r + x2r, a0i = x0i + x2i;
        float t2r = x0r - x2r, t2i = x0i - x2i;
        float a2r = t2r * cs - t2i * sn;
        float a2i = t2r * sn + t2i * cs;
        float a1r = x1r + x3r, a1i = x1i + x3i;
        float t3r = x1r - x3r, t3i = x1i - x3i;
        // W2 = -i*W1 = sn - i*cs
        float a3r = t3r * sn + t3i * cs;
        float a3i = t3i * sn - t3r * cs;
        // stage s+1 (twiddle W3 on both difference outputs)
        float y0r = a0r + a1r, y0i = a0i + a1i;
        float u1r = a0r - a1r, u1i = a0i - a1i;
        float y1r = u1r * w3c - u1i * w3s;
        float y1i = u1r * w3s + u1i * w3c;
        float y2r = a2r + a3r, y2i = a2i + a3i;
        float u3r = a2r - a3r, u3i = a2i - a3i;
        float y3r = u3r * w3c - u3i * w3s;
        float y3i = u3r * w3s + u3i * w3c;
        __syncthreads();   // (no-op ordering aid: all loads above done)
        re[iA] = y0r; im[iA] = y0i;
        re[iB] = y1r; im[iB] = y1i;
        re[iC] = y2r; im[iC] = y2i;
        re[iD] = y3r; im[iD] = y3i;
        __syncthreads();
    }

    // ---- final radix-2 stage (d=1, twiddle 1) ----
#pragma unroll
    for (int h2 = 0; h2 < 2; h2++) {
        int u = tid + h2 * 128;
        int pA = PAD(2 * u), pB = PAD(2 * u + 1);
        float ar = re[pA], ai = im[pA];
        float br = re[pB], bi = im[pB];
        re[pA] = ar + br; im[pA] = ai + bi;
        re[pB] = ar - br; im[pB] = ai - bi;
    }
    __syncthreads();

    // ---- separate ref/delta spectra, powers, local max ----
    float lmax;
    {
        float lm = 0.f;
#pragma unroll
        for (int h2 = 0; h2 < 3; h2++) {
            int k = (h2 < 2) ? (tid + h2 * 128) : 256;
            if (h2 == 2 && tid != 0) break;
            int i1 = PAD(__brev((unsigned)k) >> 23);
            int i2 = PAD(__brev((unsigned)((512 - k) & 511)) >> 23);
            float zr = re[i1], zi = im[i1];
            float mr = re[i2], mi = im[i2];
            float Rr = zr + mr, Ri = zi - mi;     // 2*ref spectrum
            float Dr = zi + mi, Di = mr - zr;     // 2*delta spectrum
            float Pa = gw2q * (Rr * Rr + Ri * Ri);
            float Pd = gw2q * (Dr * Dr + Di * Di);
            pw[k] = Pa; pdl[k] = Pd;
            lm = fmaxf(lm, Pa);
        }
        lmax = lm;
    }
#pragma unroll
    for (int o = 16; o > 0; o >>= 1)
        lmax = fmaxf(lmax, __shfl_xor_sync(0xFFFFFFFFu, lmax, o));
    if (l == 0) r1[w] = lmax;
    __syncthreads();

    // ---- pmax contribution + grid barrier (one wave; spin is safe) ----
    if (tid == 0) {
        float mx = fmaxf(fmaxf(r1[0], r1[1]), fmaxf(r1[2], r1[3]));
        atomicMax(&g_ctl.pmax, __float_as_uint(mx));
        __threadfence();
        atomicAdd(&g_ctl.done, 1u);
        unsigned v;
        do {
            asm volatile("ld.acquire.gpu.u32 %0, [%1];" : "=r"(v) : "l"(&g_ctl.done));
            if (v < (unsigned)T) __nanosleep(256);
        } while (v < (unsigned)T);
        unsigned pmu;
        asm volatile("ld.global.cg.u32 %0, [%1];" : "=r"(pmu) : "l"(&g_ctl.pmax));
        float Pmax = fmaxf(__uint_as_float(pmu), 1e-20f);
        sSC = ex2(31.890509711463527f - lg2(Pmax));   // 10^9.6 / Pmax
    }
    __syncthreads();
    float SC = sSC;

    // ---- phase 2: threshold + loss (all operands in smem) ----
    for (int ff = tid; ff < F; ff += 128) {
        sb[ff]  = g_bark[ff];
        ath[ff] = g_athpow[ff];
        pw[ff]  = SC * fmaxf(pw[ff], 1e-20f);
    }
    keepf[tid] = 1;
    mark[tid] = 0; mark[tid + 128] = 0;
    if (tid == 0) { mark[256] = 0; mark[257] = 0; }
    __syncthreads();

    // per-CTA lim (list positions 0..127) and bstart (all bins), binary search
    if (tid < 128) {
        float hv = sb[tid] + 0.5f;
        int lo = tid, hi = F;
        while (lo + 1 < hi) { int mm = (lo + hi) >> 1; if (sb[mm] < hv) lo = mm; else hi = mm; }
        slim[tid] = (short)lo;
    }
    for (int ff = tid; ff < F; ff += 128) {
        float lv = sb[ff] - 8.f;
        int lo = 0, hi = ff;
        while (lo < hi) { int mm = (lo + hi) >> 1; if (sb[mm] < lv) lo = mm + 1; else hi = mm; }
        sbs[ff] = (short)lo;
    }

    // local-max + ATH candidates
    float p3A = 0.f, p3B = 0.f;
    bool  vA = false, vB = false;
    if (tid >= 1) {
        float a = pw[tid - 1], b = pw[tid], c = pw[tid + 1];
        p3A = a + b + c;
        vA = (b > a) && (b > c) && (p3A > ath[tid]);
    }
    {
        int ff = tid + 128;
        float a = pw[ff - 1], b = pw[ff], c = pw[ff + 1];
        p3B = a + b + c;
        vB = (b > a) && (b > c) && (p3B > ath[ff]);
    }
    unsigned mA = __ballot_sync(0xFFFFFFFFu, vA);
    unsigned mB = __ballot_sync(0xFFFFFFFFu, vB);
    if (l == 0) { cnt[w] = __popc(mA); cnt[4 + w] = __popc(mB); }
    __syncthreads();
    if (tid == 0) {
        int s = 0;
        for (int c = 0; c < 8; c++) { cbase[c] = s; s += cnt[c]; }
        nsh = s;
    }
    __syncthreads();
    unsigned below = (1u << l) - 1u;
    if (vA) {
        int pos = cbase[w] + __popc(mA & below);
        order[pos] = (short)tid;
        mcv[pos]   = DB2 * lg2(p3A);
    }
    if (vB) {
        int pos = cbase[4 + w] + __popc(mB & below);
        order[pos] = (short)(tid + 128);
        mcv[pos]   = DB2 * lg2(p3B);
    }
    __syncthreads();

    // faithful sequential dedup (bark by LIST POSITION via slim[] table)
    if (tid == 0) {
        int n2 = nsh;
        if (n2 > 1) {
            int ip = 0, lp = slim[0];
            float mip = mcv[0];
            float mi_next = mcv[1];
            for (int i = 1; i < n2; i++) {
                float mi = mi_next;
                if (i + 1 < n2) mi_next = mcv[i + 1];
                if (i <= lp) {                 // close
                    if (mip < mi) {
                        keepf[ip] = 0;
                        ip++;
                        mip = mcv[ip];
                        lp  = slim[ip];
                    } else {
                        keepf[i] = 0;
                    }
                } else {
                    ip = i; mip = mi; lp = slim[i];
                }
            }
        }
    }
    __syncthreads();

    // warp 0: compact kept maskers, mark bins, parallel suffix sums (double)
    if (tid < 32) {
        int n2 = nsh, basep = 0;
        for (int c0 = 0; c0 < n2; c0 += 32) {
            int i = c0 + tid;
            bool ok = (i < n2) && keepf[i];
            unsigned mm = __ballot_sync(0xFFFFFFFFu, ok);
            if (ok) {
                int pos = basep + __popc(mm & ((1u << tid) - 1u));
                int o = order[i];
                float mv = mcv[i];
                mark[o]  = 1;
                msk[pos] = make_float4(sb[o], (mv + g_dshift[o]) * LG,
                                       fmaf(0.37f, fmaxf(mv - 40.f, 0.f), -27.f) * LG,
                                       0.f);
            }
            basep += __popc(mm);
        }
        int K = basep;
        if (tid == 0) Ksh = K;
        double carry = 0.0;
        if (K > 0) {
            for (int c0 = ((K - 1) >> 5) << 5; c0 >= 0; c0 -= 32) {
                int idx = c0 + tid;
                double p = 0.0;
                if (idx < K) {
                    float4 m4 = msk[idx];
                    float e = fmaf(-SLP, m4.x, m4.y);
                    float ei = floorf(e);
                    p = scalbn((double)ex2(e - ei), (int)ei);
                }
#pragma unroll
                for (int o = 1; o < 32; o <<= 1) {
                    double v = __shfl_down_sync(0xFFFFFFFFu, p, o);
                    if (tid + o < 32) p += v;
                }
                p += carry;
                if (idx < K) {
                    int ex; double mant = frexp(p, &ex);
                    um[idx] = make_float2((float)mant, (float)ex);
                }
                carry = __shfl_sync(0xFFFFFFFFu, p, 0);
            }
        }
        if (tid == 0) um[K] = make_float2(0.f, -1e30f);
    }
    __syncthreads();

    // exclusive prefix count of masker bins -> cum[f]
    {
        int v0 = mark[2 * tid], v1 = mark[2 * tid + 1];
        int s2 = v0 + v1;
        int incl = s2;
#pragma unroll
        for (int o = 1; o < 32; o <<= 1) {
            int u = __shfl_up_sync(0xFFFFFFFFu, incl, o);
            if (l >= o) incl += u;
        }
        if (l == 31) cnt[w] = incl;
        __syncthreads();
        if (tid == 0) {
            int b = 0;
            for (int c = 0; c < 4; c++) { cbase[c] = b; b += cnt[c]; }
        }
        __syncthreads();
        int excl = cbase[w] + incl - s2;
        cum[2 * tid]     = (short)excl;
        cum[2 * tid + 1] = (short)(excl + v0);
        if (tid == 0) cum[256] = (short)Ksh;
    }
    __syncthreads();

    float lsum = 0.f;
    for (int ff = tid; ff < F; ff += 128) {
        float bf = sb[ff];
        int j0 = cum[ff];
        int ks = cum[sbs[ff]];       // maskers >8 bark below: negligible, skip
        float sum = ath[ff];
        for (int kk = ks; kk < j0; kk++) {
            float4 m4 = msk[kk];
            sum += ex2(fmaf(m4.z, bf - m4.x, m4.y));
        }
        float2 u = um[j0];
        sum += u.x * ex2(fmaf(SLP, bf, u.y));
        float v = fmaf(SC, pdl[ff], -sum);
        if (v > 0.f) lsum += v;
    }
#pragma unroll
    for (int o = 16; o > 0; o >>= 1)
        lsum += __shfl_xor_sync(0xFFFFFFFFu, lsum, o);
    if (l == 0) r1[w] = lsum;
    __syncthreads();
    if (tid == 0) {
        g_lpart[t] = r1[0] + r1[1] + r1[2] + r1[3];
        __threadfence();
        unsigned d = atomicAdd(&g_ctl.done2, 1u);
        slast = (d == (unsigned)(T - 1)) ? 1 : 0;
    }
    __syncthreads();
    if (slast) {
        __threadfence();
        double local = 0.0;
        for (int i = tid; i < T; i += 128) local += (double)g_lpart[i];
#pragma unroll
        for (int o = 16; o > 0; o >>= 1)
            local += __shfl_xor_sync(0xFFFFFFFFu, local, o);
        if (l == 0) dred[w] = local;
        __syncthreads();
        if (tid == 0) {
            double acc = dred[0] + dred[1] + dred[2] + dred[3];
            out[0] = (float)(1e-6 * acc / (double)N);
            // self-reset for next graph replay
            g_ctl.pmax = 0u; g_ctl.done = 0u; g_ctl.done2 = 0u;
        }
    }
}

// ---------------------------------------------------------------------------
extern "C" void kernel_launch(void* const* d_in, const int* in_sizes, int n_in,
                              void* d_out, int out_size)
{
    const float* xadv = (const float*)d_in[0];
    const float* xref = (const float*)d_in[1];
    float* out = (float*)d_out;

    int L = in_sizes[0];
    int T = (L - W) / HOP + 1;
    if (T > MAXT) T = MAXT;
    int N = T * F;

    fused_kernel<<<T, 128>>>(out, xadv, xref, T, N);
}